// round 4
// baseline (speedup 1.0000x reference)
#include <cuda_runtime.h>
#include <math.h>
#include <stdint.h>

#define D      512
#define STEPS  6
#define NROWS  100000
#define GA     592      // attend grid: 148 SMs * 4 blocks
#define WPB    8        // warps per block (256 threads)

// ---------------- persistent device state (no allocations allowed) ----------
__device__ float g_h[D];
__device__ float g_c[D];
__device__ float g_pm[GA];            // per-block running max
__device__ float g_ps[GA];            // per-block exp-sum
__device__ float g_pctx[D * GA];      // per-block ctx partials, layout [j][block] for coalesced combine
__device__ float g_inp[2 * D];        // [ctx | h] snapshot for the LSTM GEMV
__device__ float g_ctx_steps[STEPS * D];
__device__ float g_gates[4 * D];
__device__ float g_logits[D];
__device__ unsigned g_cnt_gates = 0;
__device__ unsigned g_cnt_final = 0;

__device__ __forceinline__ float dot4(float4 a, float4 b) {
    return a.x * b.x + a.y * b.y + a.z * b.z + a.w * b.w;
}

__device__ __forceinline__ float warp_sum(float v) {
#pragma unroll
    for (int o = 16; o > 0; o >>= 1) v += __shfl_xor_sync(0xffffffffu, v, o);
    return v;
}
__device__ __forceinline__ float warp_max(float v) {
#pragma unroll
    for (int o = 16; o > 0; o >>= 1) v = fmaxf(v, __shfl_xor_sync(0xffffffffu, v, o));
    return v;
}

// ---------------- init: zero h, c (graph-replay determinism) ----------------
__global__ void init_kernel() {
    int t = threadIdx.x;
    for (int j = t; j < D; j += blockDim.x) { g_h[j] = 0.f; g_c[j] = 0.f; }
    if (t == 0) { g_cnt_gates = 0; g_cnt_final = 0; }
}

// ---------------- kernel A: single-pass online-softmax attention ------------
// warp-per-row grid-stride; each warp keeps (m, s, ctx[16 floats/lane]).
__global__ void __launch_bounds__(256, 4) attend_kernel(const float* __restrict__ x) {
    __shared__ float4 sh_h[D / 4];            // 2 KB
    __shared__ float  sm_wm[WPB], sm_ws[WPB];
    __shared__ float4 sm_acc[WPB][D / 4];     // 16 KB

    const int tid = threadIdx.x, w = tid >> 5, l = tid & 31;

    if (tid < D / 4) sh_h[tid] = reinterpret_cast<const float4*>(g_h)[tid];
    __syncthreads();

    float4 h4[4];
#pragma unroll
    for (int k = 0; k < 4; k++) h4[k] = sh_h[k * 32 + l];

    float m = -INFINITY, s = 0.f;
    float4 acc[4];
#pragma unroll
    for (int k = 0; k < 4; k++) acc[k] = make_float4(0.f, 0.f, 0.f, 0.f);

    const int TW = GA * WPB;  // total warps
    for (int row = blockIdx.x * WPB + w; row < NROWS; row += TW) {
        const float4* xr = reinterpret_cast<const float4*>(x + (size_t)row * D);
        float4 rx[4];
#pragma unroll
        for (int k = 0; k < 4; k++) rx[k] = xr[k * 32 + l];

        float d = 0.f;
#pragma unroll
        for (int k = 0; k < 4; k++) d += dot4(rx[k], h4[k]);
        d = warp_sum(d);                       // warp-uniform score

        if (d > m) {                           // uniform branch
            float f = __expf(m - d);           // exp(-inf)=0 on first row
            s *= f;
#pragma unroll
            for (int k = 0; k < 4; k++) {
                acc[k].x *= f; acc[k].y *= f; acc[k].z *= f; acc[k].w *= f;
            }
            m = d;
        }
        float wgt = __expf(d - m);
        s += wgt;
#pragma unroll
        for (int k = 0; k < 4; k++) {
            acc[k].x += wgt * rx[k].x; acc[k].y += wgt * rx[k].y;
            acc[k].z += wgt * rx[k].z; acc[k].w += wgt * rx[k].w;
        }
    }

    // block-level merge of 8 warps
    if (l == 0) { sm_wm[w] = m; sm_ws[w] = s; }
#pragma unroll
    for (int k = 0; k < 4; k++) sm_acc[w][k * 32 + l] = acc[k];
    __syncthreads();

    float M = sm_wm[0];
#pragma unroll
    for (int i = 1; i < WPB; i++) M = fmaxf(M, sm_wm[i]);

    if (tid == 0) {
        float S = 0.f;
#pragma unroll
        for (int i = 0; i < WPB; i++) S += __expf(sm_wm[i] - M) * sm_ws[i];
        g_pm[blockIdx.x] = M;
        g_ps[blockIdx.x] = S;
    }

    float fac[WPB];
#pragma unroll
    for (int i = 0; i < WPB; i++) fac[i] = __expf(sm_wm[i] - M);

    for (int j = tid; j < D; j += 256) {
        float v = 0.f;
#pragma unroll
        for (int i = 0; i < WPB; i++)
            v += fac[i] * reinterpret_cast<const float*>(sm_acc[i])[j];
        g_pctx[(size_t)j * GA + blockIdx.x] = v;   // transposed for combine
    }
}

// ---------------- kernel B: merge GA partials -> ctx, snapshot inp ----------
__global__ void __launch_bounds__(256) combine_kernel(int step) {
    __shared__ float red[WPB];
    const int tid = threadIdx.x, w = tid >> 5, l = tid & 31;

    // global max over block maxes
    float lm = -INFINITY;
    for (int b = tid; b < GA; b += 256) lm = fmaxf(lm, g_pm[b]);
    lm = warp_max(lm);
    if (l == 0) red[w] = lm;
    __syncthreads();
    float M = red[0];
#pragma unroll
    for (int i = 1; i < WPB; i++) M = fmaxf(M, red[i]);
    __syncthreads();

    // global exp-sum
    float ls = 0.f;
    for (int b = tid; b < GA; b += 256) ls += __expf(g_pm[b] - M) * g_ps[b];
    ls = warp_sum(ls);
    if (l == 0) red[w] = ls;
    __syncthreads();
    float S = 0.f;
#pragma unroll
    for (int i = 0; i < WPB; i++) S += red[i];

    // warp per output element j; lanes stride over blocks (coalesced)
    const int j = blockIdx.x * WPB + w;   // 64 blocks * 8 = 512
    float v = 0.f;
    for (int b = l; b < GA; b += 32) v += __expf(g_pm[b] - M) * g_pctx[(size_t)j * GA + b];
    v = warp_sum(v);
    if (l == 0) {
        float ctx = v / S;
        g_inp[j]            = ctx;
        g_ctx_steps[step * D + j] = ctx;
        g_inp[D + j]        = g_h[j];     // h snapshot (pre-update)
    }
}

// ---------------- kernel C: gates GEMV + last-block LSTM update -------------
__global__ void __launch_bounds__(256) gates_kernel(const float* __restrict__ W_ih,
                                                    const float* __restrict__ W_hh,
                                                    const float* __restrict__ b_ih,
                                                    const float* __restrict__ b_hh) {
    __shared__ float4 s_inp[2 * D / 4];   // 256 float4 = 1024 floats
    __shared__ bool   s_last;
    const int tid = threadIdx.x, w = tid >> 5, l = tid & 31;

    s_inp[tid] = reinterpret_cast<const float4*>(g_inp)[tid];
    __syncthreads();

    const int r = blockIdx.x * WPB + w;   // 256 blocks * 8 = 2048 rows
    const float4* wih = reinterpret_cast<const float4*>(W_ih + (size_t)r * (2 * D));
    float d = 0.f;
#pragma unroll
    for (int k = 0; k < 8; k++) d += dot4(wih[k * 32 + l], s_inp[k * 32 + l]);
    const float4* whh = reinterpret_cast<const float4*>(W_hh + (size_t)r * D);
#pragma unroll
    for (int k = 0; k < 4; k++) d += dot4(whh[k * 32 + l], s_inp[128 + k * 32 + l]);
    d = warp_sum(d);
    if (l == 0) g_gates[r] = d + b_ih[r] + b_hh[r];

    __threadfence();
    __syncthreads();
    if (tid == 0) {
        unsigned v = atomicAdd(&g_cnt_gates, 1u);
        s_last = (v == gridDim.x - 1);
    }
    __syncthreads();

    if (s_last) {
        __threadfence();
        for (int j = tid; j < D; j += 256) {
            float gi = g_gates[j];
            float gf = g_gates[D + j];
            float gg = g_gates[2 * D + j];
            float go = g_gates[3 * D + j];
            float ig = 1.f / (1.f + expf(-gi));
            float fg = 1.f / (1.f + expf(-gf));
            float gv = tanhf(gg);
            float og = 1.f / (1.f + expf(-go));
            float c  = fg * g_c[j] + ig * gv;
            g_c[j] = c;
            g_h[j] = og * tanhf(c);
        }
        if (tid == 0) g_cnt_gates = 0;   // reset for next step / next replay
    }
}

// ---------------- final: projection GEMV + last-block softmax ---------------
__global__ void __launch_bounds__(256) final_kernel(const float* __restrict__ W_proj,
                                                    const float* __restrict__ b_proj,
                                                    float* __restrict__ out) {
    __shared__ float4 s_ctx[STEPS * D / 4];  // 768 float4 = 12 KB
    __shared__ bool   s_last;
    const int tid = threadIdx.x, w = tid >> 5, l = tid & 31;

    for (int i = tid; i < STEPS * D / 4; i += 256)
        s_ctx[i] = reinterpret_cast<const float4*>(g_ctx_steps)[i];
    __syncthreads();

    const int r = blockIdx.x * WPB + w;   // 64 blocks * 8 = 512 rows
    const float4* wp = reinterpret_cast<const float4*>(W_proj + (size_t)r * (STEPS * D));
    float d = 0.f;
#pragma unroll
    for (int k = 0; k < 24; k++) d += dot4(wp[k * 32 + l], s_ctx[k * 32 + l]);
    d = warp_sum(d);
    if (l == 0) g_logits[r] = d + b_proj[r];

    __threadfence();
    __syncthreads();
    if (tid == 0) {
        unsigned v = atomicAdd(&g_cnt_final, 1u);
        s_last = (v == gridDim.x - 1);
    }
    __syncthreads();

    if (s_last) {
        __threadfence();
        __shared__ float red[WPB];
        float lm = -INFINITY;
        for (int j = tid; j < D; j += 256) lm = fmaxf(lm, g_logits[j]);
        lm = warp_max(lm);
        if (l == 0) red[w] = lm;
        __syncthreads();
        float M = red[0];
#pragma unroll
        for (int i = 1; i < WPB; i++) M = fmaxf(M, red[i]);
        __syncthreads();
        float ls = 0.f;
        for (int j = tid; j < D; j += 256) ls += expf(g_logits[j] - M);
        ls = warp_sum(ls);
        if (l == 0) red[w] = ls;
        __syncthreads();
        float S = 0.f;
#pragma unroll
        for (int i = 0; i < WPB; i++) S += red[i];
        for (int j = tid; j < D; j += 256) out[j] = expf(g_logits[j] - M) / S;
        if (tid == 0) g_cnt_final = 0;
    }
}

// ---------------- launch --------------------------------------------------
extern "C" void kernel_launch(void* const* d_in, const int* in_sizes, int n_in,
                              void* d_out, int out_size) {
    const float* x      = (const float*)d_in[0];
    const float* W_ih   = (const float*)d_in[1];
    const float* W_hh   = (const float*)d_in[2];
    const float* b_ih   = (const float*)d_in[3];
    const float* b_hh   = (const float*)d_in[4];
    const float* W_proj = (const float*)d_in[5];
    const float* b_proj = (const float*)d_in[6];
    float* out = (float*)d_out;

    init_kernel<<<1, 256>>>();
    for (int step = 0; step < STEPS; step++) {
        attend_kernel<<<GA, 256>>>(x);
        combine_kernel<<<64, 256>>>(step);
        gates_kernel<<<256, 256>>>(W_ih, W_hh, b_ih, b_hh);
    }
    final_kernel<<<64, 256>>>(W_proj, b_proj, out);
}